// round 2
// baseline (speedup 1.0000x reference)
#include <cuda_runtime.h>

#define N_TOKENS  131072
#define NUM_CODES 1024
#define CODE_DIM  64
#define DECAY     0.99f
#define OMD       0.01f
#define EPS       1e-5f

// Output layout (f32, concatenated in reference return order)
#define OUT_Q     0
#define OUT_IDX   (N_TOKENS * CODE_DIM)
#define OUT_LOSS  (OUT_IDX + N_TOKENS)
#define OUT_CB    (OUT_LOSS + 1)
#define OUT_CS    (OUT_CB + NUM_CODES * CODE_DIM)
#define OUT_EMA   (OUT_CS + NUM_CODES)

typedef unsigned long long u64;

__device__ float g_dw[NUM_CODES * CODE_DIM];
__device__ float g_counts[NUM_CODES];
__device__ float g_cnorm[NUM_CODES];
__device__ float g_loss;

// ---------------- f32x2 packed-math helpers ----------------
__device__ __forceinline__ u64 pk2(float x, float y) {
    u64 r; asm("mov.b64 %0, {%1, %2};" : "=l"(r) : "f"(x), "f"(y)); return r;
}
__device__ __forceinline__ void upk2(u64 v, float& x, float& y) {
    asm("mov.b64 {%0, %1}, %2;" : "=f"(x), "=f"(y) : "l"(v));
}
__device__ __forceinline__ u64 fma2(u64 a, u64 b, u64 c) {
    u64 r; asm("fma.rn.f32x2 %0, %1, %2, %3;" : "=l"(r) : "l"(a), "l"(b), "l"(c)); return r;
}

// ---------------- prep: zero scratch + precompute ||c||^2 ----------------
__global__ void prep_kernel(const float4* __restrict__ cb4) {
    int i = blockIdx.x * 256 + threadIdx.x;   // 65536 threads
    g_dw[i] = 0.0f;
    if (i < NUM_CODES) {
        g_counts[i] = 0.0f;
        float s = 0.0f;
        const float4* c = cb4 + i * 16;
#pragma unroll
        for (int j = 0; j < 16; j++) {
            float4 v = c[j];
            s += v.x * v.x + v.y * v.y + v.z * v.z + v.w * v.w;
        }
        g_cnorm[i] = s;
    }
    if (i == 0) g_loss = 0.0f;
}

// ---------------- assign: register-tiled distance GEMM + argmin ----------------
// Block: 256 threads, 128 tokens, all 1024 codes (8 tiles of 128).
// Thread tile: 8 tokens (4 f32x2 pairs) x 8 codes = 32 f32x2 accumulators.
// tg = tid>>4 (token group, 16), cg = tid&15 (code group, 16).
// Smem layout (dynamic):
//   zt  : u64[64*64]    z packed pairs, [d][pair]        32768 B
//   cbs : u64[64*128]   code dup pairs, [d][code]        65536 B
//   cns : float[128]                                     512 B
//   sidx: int[128]                                       512 B
//   red : float[256]                                     1024 B
#define SMEM_BYTES (32768 + 65536 + 512 + 512 + 1024)

__global__ void __launch_bounds__(256, 2)
assign_kernel(const float4* __restrict__ z4, const float4* __restrict__ cb4,
              float* __restrict__ out) {
    extern __shared__ char smem[];
    u64*   zt   = (u64*)smem;
    u64*   cbs  = zt + 64 * 64;
    float* cns  = (float*)(cbs + 64 * 128);
    int*   sidx = (int*)(cns + 128);
    float* red  = (float*)(sidx + 128);
    float* ztf  = (float*)zt;

    const int tid  = threadIdx.x;
    const int tg   = tid >> 4;
    const int cg   = tid & 15;
    const int base = blockIdx.x * 128;

    // ---- load z tile into packed-pair smem: zt[d*64 + p] = (z[2p][d], z[2p+1][d])
    for (int l = tid; l < 2048; l += 256) {
        int t = l & 127, j = l >> 7;            // t: token 0..127, j: float4 idx 0..15
        float4 v = z4[(base + t) * 16 + j];
        int p = t >> 1, par = t & 1;
        ztf[((4 * j + 0) * 64 + p) * 2 + par] = v.x;
        ztf[((4 * j + 1) * 64 + p) * 2 + par] = v.y;
        ztf[((4 * j + 2) * 64 + p) * 2 + par] = v.z;
        ztf[((4 * j + 3) * 64 + p) * 2 + par] = v.w;
    }

    float best[8];
    int   bi[8];
#pragma unroll
    for (int t = 0; t < 8; t++) { best[t] = 3.0e38f; bi[t] = 0; }

    for (int tile = 0; tile < 8; tile++) {
        const int kb = tile * 128;
        __syncthreads();
        // ---- load 128-code tile, duplicated pairs: cbs[d*128 + k] = (c,c)
        for (int l = tid; l < 2048; l += 256) {
            int k = l & 127, j = l >> 7;
            float4 v = cb4[(kb + k) * 16 + j];
            cbs[(4 * j + 0) * 128 + k] = pk2(v.x, v.x);
            cbs[(4 * j + 1) * 128 + k] = pk2(v.y, v.y);
            cbs[(4 * j + 2) * 128 + k] = pk2(v.z, v.z);
            cbs[(4 * j + 3) * 128 + k] = pk2(v.w, v.w);
        }
        if (tid < 128) cns[tid] = g_cnorm[kb + tid];
        __syncthreads();

        // ---- accumulate dots: acc[p*8+c] over d
        u64 acc[32];
#pragma unroll
        for (int i = 0; i < 32; i++) acc[i] = 0ull;

#pragma unroll 8
        for (int d = 0; d < 64; d++) {
            ulonglong2 za = *(const ulonglong2*)&zt[d * 64 + tg * 4];
            ulonglong2 zb = *(const ulonglong2*)&zt[d * 64 + tg * 4 + 2];
            ulonglong2 c0 = *(const ulonglong2*)&cbs[d * 128 + cg * 8];
            ulonglong2 c1 = *(const ulonglong2*)&cbs[d * 128 + cg * 8 + 2];
            ulonglong2 c2 = *(const ulonglong2*)&cbs[d * 128 + cg * 8 + 4];
            ulonglong2 c3 = *(const ulonglong2*)&cbs[d * 128 + cg * 8 + 6];
            u64 zp0 = za.x, zp1 = za.y, zp2 = zb.x, zp3 = zb.y;
            u64 cd[8] = {c0.x, c0.y, c1.x, c1.y, c2.x, c2.y, c3.x, c3.y};
#pragma unroll
            for (int c = 0; c < 8; c++) {
                acc[0 * 8 + c] = fma2(zp0, cd[c], acc[0 * 8 + c]);
                acc[1 * 8 + c] = fma2(zp1, cd[c], acc[1 * 8 + c]);
                acc[2 * 8 + c] = fma2(zp2, cd[c], acc[2 * 8 + c]);
                acc[3 * 8 + c] = fma2(zp3, cd[c], acc[3 * 8 + c]);
            }
        }

        // ---- epilogue: score = ||c||^2 - 2*dot, running argmin
        const u64 NEG2 = pk2(-2.0f, -2.0f);
#pragma unroll
        for (int c = 0; c < 8; c++) {
            float cn = cns[cg * 8 + c];
            u64 cn2 = pk2(cn, cn);
            int kg = kb + cg * 8 + c;
#pragma unroll
            for (int p = 0; p < 4; p++) {
                u64 sc = fma2(acc[p * 8 + c], NEG2, cn2);
                float s0, s1;
                upk2(sc, s0, s1);
                if (s0 < best[2 * p])     { best[2 * p] = s0;     bi[2 * p] = kg; }
                if (s1 < best[2 * p + 1]) { best[2 * p + 1] = s1; bi[2 * p + 1] = kg; }
            }
        }
    }

    // ---- cross-lane reduce over the 16 code-groups (lanes share tg; cg = lane&15)
    float myBest = 0.0f;
    int   myIdx  = 0;
#pragma unroll
    for (int t = 0; t < 8; t++) {
        float v = best[t];
        int   i = bi[t];
#pragma unroll
        for (int off = 8; off > 0; off >>= 1) {
            float ov = __shfl_xor_sync(0xffffffffu, v, off);
            int   oi = __shfl_xor_sync(0xffffffffu, i, off);
            if (ov < v || (ov == v && oi < i)) { v = ov; i = oi; }
        }
        if (cg == t) { myBest = v; myIdx = i; }
    }

    // ---- per-token outputs by handling lane (cg < 8 handles token tg*8+cg)
    float lpart = 0.0f;
    if (cg < 8) {
        int tl  = tg * 8 + cg;      // local token
        int tok = base + tl;
        sidx[tl] = myIdx;
        out[OUT_IDX + tok] = (float)myIdx;
        atomicAdd(&g_counts[myIdx], 1.0f);
        int p = tl >> 1, par = tl & 1;
        float zn = 0.0f;
        float* dwp = &g_dw[myIdx * 64];
#pragma unroll 8
        for (int d = 0; d < 64; d++) {
            float zv = ztf[(d * 64 + p) * 2 + par];
            zn += zv * zv;
            atomicAdd(&dwp[d], zv);
        }
        lpart = zn + myBest;        // exact d2min for commitment loss
    }
    red[tid] = lpart;
    __syncthreads();
    for (int s = 128; s > 0; s >>= 1) {
        if (tid < s) red[tid] += red[tid + s];
        __syncthreads();
    }
    if (tid == 0) atomicAdd(&g_loss, red[0]);

    // ---- cooperative coalesced quantized write: out_q[token] = codebook[idx]
    float4* outq = (float4*)out;   // OUT_Q == 0
    for (int l = tid; l < 2048; l += 256) {
        int t = l >> 4, j = l & 15;
        outq[(base + t) * 16 + j] = cb4[sidx[t] * 16 + j];
    }
}

// ---------------- finalize: EMA updates + codebook normalize + loss ----------------
__global__ void finalize_kernel(const float* __restrict__ cs_in,
                                const float* __restrict__ ema_in,
                                float* __restrict__ out) {
    __shared__ float s[1024];
    int k = threadIdx.x;
    float ncs = DECAY * cs_in[k] + OMD * g_counts[k];
    s[k] = ncs;
    __syncthreads();
    for (int st = 512; st > 0; st >>= 1) {
        if (k < st) s[k] += s[k + st];
        __syncthreads();
    }
    float n   = s[0];
    float csk = (ncs + EPS) / (n + NUM_CODES * EPS) * n;
    out[OUT_CS + k] = ncs;
    float inv = 1.0f / csk;
#pragma unroll 4
    for (int d = 0; d < 64; d++) {
        float e = DECAY * ema_in[k * 64 + d] + OMD * g_dw[k * 64 + d];
        out[OUT_EMA + k * 64 + d] = e;
        out[OUT_CB + k * 64 + d]  = e * inv;
    }
    if (k == 0) out[OUT_LOSS] = g_loss * (1.0f / (float)(N_TOKENS * CODE_DIM));
}

extern "C" void kernel_launch(void* const* d_in, const int* in_sizes, int n_in,
                              void* d_out, int out_size) {
    const float* z   = (const float*)d_in[0];
    const float* cb  = (const float*)d_in[1];
    const float* cs  = (const float*)d_in[2];
    const float* ema = (const float*)d_in[3];
    float* out = (float*)d_out;

    static int smem_set = 0;
    if (!smem_set) {
        cudaFuncSetAttribute(assign_kernel,
                             cudaFuncAttributeMaxDynamicSharedMemorySize, SMEM_BYTES);
        smem_set = 1;
    }

    prep_kernel<<<256, 256>>>((const float4*)cb);
    assign_kernel<<<1024, 256, SMEM_BYTES>>>((const float4*)z, (const float4*)cb, out);
    finalize_kernel<<<1, 1024>>>(cs, ema, out);
}

// round 4
// speedup vs baseline: 1.8243x; 1.8243x over previous
#include <cuda_runtime.h>
#include <cuda_bf16.h>
#include <cstdint>

#define N_TOKENS  131072
#define NUM_CODES 1024
#define CODE_DIM  64
#define DECAY     0.99f
#define OMD       0.01f
#define EPS       1e-5f

#define OUT_Q     0
#define OUT_IDX   (N_TOKENS * CODE_DIM)
#define OUT_LOSS  (OUT_IDX + N_TOKENS)
#define OUT_CB    (OUT_LOSS + 1)
#define OUT_CS    (OUT_CB + NUM_CODES * CODE_DIM)
#define OUT_EMA   (OUT_CS + NUM_CODES)

#define MARGIN 2.0f
#define CAP    16
#define CHUNK  64
#define NCHUNK 16

// ---------------- device scratch ----------------
__device__ __align__(16) __nv_bfloat16 g_zh[N_TOKENS * CODE_DIM];
__device__ __align__(16) __nv_bfloat16 g_cbh[NUM_CODES * CODE_DIM];
__device__ float g_dw[NUM_CODES * CODE_DIM];
__device__ float g_counts[NUM_CODES];
__device__ float g_cnorm[NUM_CODES];
__device__ float g_loss;

// ---------------- helpers ----------------
__device__ __forceinline__ uint32_t smem_u32(const void* p) {
    uint32_t a;
    asm("{ .reg .u64 t; cvta.to.shared.u64 t, %1; cvt.u32.u64 %0, t; }" : "=r"(a) : "l"(p));
    return a;
}
__device__ __forceinline__ void ldsm_x4(uint32_t& r0, uint32_t& r1, uint32_t& r2,
                                        uint32_t& r3, uint32_t addr) {
    asm volatile("ldmatrix.sync.aligned.m8n8.x4.shared.b16 {%0,%1,%2,%3}, [%4];"
                 : "=r"(r0), "=r"(r1), "=r"(r2), "=r"(r3) : "r"(addr));
}
__device__ __forceinline__ void mma16816(float* c, const uint32_t* a,
                                         uint32_t b0, uint32_t b1) {
    asm volatile(
        "mma.sync.aligned.m16n8k16.row.col.f32.bf16.bf16.f32 "
        "{%0,%1,%2,%3}, {%4,%5,%6,%7}, {%8,%9}, {%0,%1,%2,%3};"
        : "+f"(c[0]), "+f"(c[1]), "+f"(c[2]), "+f"(c[3])
        : "r"(a[0]), "r"(a[1]), "r"(a[2]), "r"(a[3]), "r"(b0), "r"(b1));
}
__device__ __forceinline__ unsigned bf2u(__nv_bfloat16 a, __nv_bfloat16 b) {
    __nv_bfloat162 p(a, b);
    return *(unsigned*)&p;
}

// ---------------- prep: codebook bf16 + cnorm + zero scratch ----------------
__global__ void prep_cb_kernel(const float4* __restrict__ cb4) {
    int i = blockIdx.x * 256 + threadIdx.x;   // 16384 threads
    float4 v = cb4[i];
    uint2 o;
    o.x = bf2u(__float2bfloat16_rn(v.x), __float2bfloat16_rn(v.y));
    o.y = bf2u(__float2bfloat16_rn(v.z), __float2bfloat16_rn(v.w));
    ((uint2*)g_cbh)[i] = o;
    ((float4*)g_dw)[i] = make_float4(0.f, 0.f, 0.f, 0.f);
    if (i < NUM_CODES) {
        g_counts[i] = 0.0f;
        float s = 0.0f;
        const float4* c = cb4 + i * 16;
#pragma unroll
        for (int j = 0; j < 16; j++) {
            float4 w = c[j];
            s += w.x * w.x + w.y * w.y + w.z * w.z + w.w * w.w;
        }
        g_cnorm[i] = s;
    }
    if (i == 0) g_loss = 0.0f;
}

// ---------------- prep: z bf16 ----------------
__global__ void prep_z_kernel(const float4* __restrict__ z4) {
    int i = blockIdx.x * 256 + threadIdx.x;   // 2,097,152 threads
    float4 v = z4[i];
    uint2 o;
    o.x = bf2u(__float2bfloat16_rn(v.x), __float2bfloat16_rn(v.y));
    o.y = bf2u(__float2bfloat16_rn(v.z), __float2bfloat16_rn(v.w));
    ((uint2*)g_zh)[i] = o;
}

// ---------------- assign: bf16 mma approx + margin candidates + exact rescore ----------------
// 128 threads (4 warps), 128 tokens/CTA. Warp w owns tokens w*32..w*32+31.
// Codes processed in 16 chunks of 64 via smem. Rows padded to 144B (conflict-free ldmatrix).
__global__ void __launch_bounds__(128)
assign_kernel(const float4* __restrict__ z4, const float4* __restrict__ cb4,
              float* __restrict__ out) {
    __shared__ __align__(16) unsigned char As[128 * 144];
    __shared__ __align__(16) unsigned char Bs[64 * 144];
    __shared__ float cns[CHUNK];
    __shared__ unsigned cnt[128];
    __shared__ unsigned short cand[128 * CAP];

    const int tid  = threadIdx.x;
    const int w    = tid >> 5;
    const int lane = tid & 31;
    const int base = blockIdx.x * 128;
    const uint32_t AsA = smem_u32(As);
    const uint32_t BsA = smem_u32(Bs);

    cnt[tid] = 0u;

    // ---- stage z bf16 tile into As (128 rows x 128B, stride 144)
    {
        const uint4* src = (const uint4*)(g_zh + (size_t)base * CODE_DIM);
#pragma unroll
        for (int i = 0; i < 8; i++) {
            int l = tid + i * 128;          // 1024 uint4
            int row = l >> 3, j = l & 7;
            *(uint4*)(As + row * 144 + j * 16) = src[row * 8 + j];
        }
    }

    // ---- prefetch B chunk 0
    uint4 pre[4];
    float cnpre = 0.0f;
    {
        const uint4* src = (const uint4*)g_cbh;
#pragma unroll
        for (int i = 0; i < 4; i++) {
            int l = tid + i * 128;
            int row = l >> 3, j = l & 7;
            pre[i] = src[row * 8 + j];
        }
        if (tid < CHUNK) cnpre = g_cnorm[tid];
    }

    __syncthreads();   // As visible

    // ---- load A fragments once: af[mt][ks][4]
    uint32_t af[2][4][4];
#pragma unroll
    for (int mt = 0; mt < 2; mt++) {
#pragma unroll
        for (int ks = 0; ks < 4; ks++) {
            uint32_t addr = AsA + (w * 32 + mt * 16 + (lane & 15)) * 144
                          + ((lane >> 4) << 4) + ks * 32;
            ldsm_x4(af[mt][ks][0], af[mt][ks][1], af[mt][ks][2], af[mt][ks][3], addr);
        }
    }

    float rb[4];       // running approx best per (mt, accpair) token row
#pragma unroll
    for (int i = 0; i < 4; i++) rb[i] = 3.0e38f;

    for (int c = 0; c < NCHUNK; c++) {
        const int kb = c * CHUNK;
        __syncthreads();   // prior chunk's compute done reading Bs/cns
#pragma unroll
        for (int i = 0; i < 4; i++) {
            int l = tid + i * 128;
            int row = l >> 3, j = l & 7;
            *(uint4*)(Bs + row * 144 + j * 16) = pre[i];
        }
        if (tid < CHUNK) cns[tid] = cnpre;
        __syncthreads();   // Bs ready

        if (c < NCHUNK - 1) {
            const uint4* src = (const uint4*)(g_cbh + (size_t)(kb + CHUNK) * CODE_DIM);
#pragma unroll
            for (int i = 0; i < 4; i++) {
                int l = tid + i * 128;
                int row = l >> 3, j = l & 7;
                pre[i] = src[row * 8 + j];
            }
            if (tid < CHUNK) cnpre = g_cnorm[kb + CHUNK + tid];
        }

        // ---- MMA: acc[mt][nt][4]
        float acc[2][8][4];
#pragma unroll
        for (int mt = 0; mt < 2; mt++)
#pragma unroll
            for (int nt = 0; nt < 8; nt++)
#pragma unroll
                for (int i = 0; i < 4; i++) acc[mt][nt][i] = 0.0f;

#pragma unroll
        for (int nt = 0; nt < 8; nt++) {
            uint32_t b[8];
            uint32_t baddr = BsA + (nt * 8 + (lane & 7)) * 144 + ((lane >> 3) << 4);
            ldsm_x4(b[0], b[1], b[2], b[3], baddr);        // ksteps 0,1
            ldsm_x4(b[4], b[5], b[6], b[7], baddr + 64);   // ksteps 2,3
#pragma unroll
            for (int mt = 0; mt < 2; mt++) {
                mma16816(acc[mt][nt], af[mt][0], b[0], b[1]);
                mma16816(acc[mt][nt], af[mt][1], b[2], b[3]);
                mma16816(acc[mt][nt], af[mt][2], b[4], b[5]);
                mma16816(acc[mt][nt], af[mt][3], b[6], b[7]);
            }
        }

        // ---- epilogue: scores s = cn - 2*dot; running min + margin candidates
        float cnv[8][2];
#pragma unroll
        for (int nt = 0; nt < 8; nt++) {
            float2 v = *(const float2*)&cns[nt * 8 + 2 * (lane & 3)];
            cnv[nt][0] = v.x; cnv[nt][1] = v.y;
        }
#pragma unroll
        for (int mt = 0; mt < 2; mt++) {
#pragma unroll
            for (int ap = 0; ap < 2; ap++) {
                float mn = 3.0e38f;
#pragma unroll
                for (int nt = 0; nt < 8; nt++) {
#pragma unroll
                    for (int i = 0; i < 2; i++) {
                        float s = fmaf(-2.0f, acc[mt][nt][ap * 2 + i], cnv[nt][i]);
                        mn = fminf(mn, s);
                    }
                }
                mn = fminf(mn, __shfl_xor_sync(0xffffffffu, mn, 1));
                mn = fminf(mn, __shfl_xor_sync(0xffffffffu, mn, 2));
                float r = fminf(rb[mt * 2 + ap], mn);
                rb[mt * 2 + ap] = r;
                float thr = r + MARGIN;
                int tok_l = w * 32 + mt * 16 + (lane >> 2) + 8 * ap;
#pragma unroll
                for (int nt = 0; nt < 8; nt++) {
#pragma unroll
                    for (int i = 0; i < 2; i++) {
                        float s = fmaf(-2.0f, acc[mt][nt][ap * 2 + i], cnv[nt][i]);
                        if (s <= thr) {
                            unsigned slot = atomicAdd(&cnt[tok_l], 1u);
                            if (slot < CAP)
                                cand[tok_l * CAP + slot] =
                                    (unsigned short)(kb + nt * 8 + 2 * (lane & 3) + i);
                        }
                    }
                }
            }
        }
    }
    __syncthreads();

    // ---- phase B: exact fp32 rescore of candidates (thread owns token base+tid)
    const int tok = base + tid;
    float zr[64];
    {
        const float4* zsrc = z4 + (size_t)tok * 16;
#pragma unroll
        for (int j = 0; j < 16; j++) {
            float4 v = zsrc[j];
            zr[4 * j + 0] = v.x; zr[4 * j + 1] = v.y;
            zr[4 * j + 2] = v.z; zr[4 * j + 3] = v.w;
        }
    }
    float zn = 0.0f;
#pragma unroll
    for (int d = 0; d < 64; d++) zn += zr[d] * zr[d];

    float best = 3.0e38f;
    int   bk   = 0;
    unsigned n = cnt[tid];
    if (n > 0 && n <= CAP) {
        for (unsigned u = 0; u < n; u++) {
            int k = cand[tid * CAP + u];
            const float4* cr = cb4 + (size_t)k * 16;
            float dot = 0.0f;
#pragma unroll
            for (int j = 0; j < 16; j++) {
                float4 v = cr[j];
                dot += zr[4 * j + 0] * v.x + zr[4 * j + 1] * v.y
                     + zr[4 * j + 2] * v.z + zr[4 * j + 3] * v.w;
            }
            float s = fmaf(-2.0f, dot, g_cnorm[k]);
            if (s < best || (s == best && k < bk)) { best = s; bk = k; }
        }
    } else {
        // overflow (or impossible empty): full exact scan
        for (int k = 0; k < NUM_CODES; k++) {
            const float4* cr = cb4 + (size_t)k * 16;
            float dot = 0.0f;
#pragma unroll
            for (int j = 0; j < 16; j++) {
                float4 v = cr[j];
                dot += zr[4 * j + 0] * v.x + zr[4 * j + 1] * v.y
                     + zr[4 * j + 2] * v.z + zr[4 * j + 3] * v.w;
            }
            float s = fmaf(-2.0f, dot, g_cnorm[k]);
            if (s < best) { best = s; bk = k; }
        }
    }

    // ---- outputs + scatter stats
    out[OUT_IDX + tok] = (float)bk;
    atomicAdd(&g_counts[bk], 1.0f);
    float4* outq = (float4*)out;   // OUT_Q == 0
    const float4* cbest = cb4 + (size_t)bk * 16;
    float* dwp = &g_dw[bk * 64];
#pragma unroll
    for (int j = 0; j < 16; j++) {
        outq[(size_t)tok * 16 + j] = cbest[j];
        atomicAdd(&dwp[4 * j + 0], zr[4 * j + 0]);
        atomicAdd(&dwp[4 * j + 1], zr[4 * j + 1]);
        atomicAdd(&dwp[4 * j + 2], zr[4 * j + 2]);
        atomicAdd(&dwp[4 * j + 3], zr[4 * j + 3]);
    }

    float lp = zn + best;   // exact d2min
#pragma unroll
    for (int off = 16; off > 0; off >>= 1)
        lp += __shfl_down_sync(0xffffffffu, lp, off);
    if (lane == 0) atomicAdd(&g_loss, lp);
}

// ---------------- finalize ----------------
__global__ void finalize_kernel(const float* __restrict__ cs_in,
                                const float* __restrict__ ema_in,
                                float* __restrict__ out) {
    __shared__ float s[1024];
    int k = threadIdx.x;
    float ncs = DECAY * cs_in[k] + OMD * g_counts[k];
    s[k] = ncs;
    __syncthreads();
    for (int st = 512; st > 0; st >>= 1) {
        if (k < st) s[k] += s[k + st];
        __syncthreads();
    }
    float n   = s[0];
    float csk = (ncs + EPS) / (n + NUM_CODES * EPS) * n;
    out[OUT_CS + k] = ncs;
    float inv = 1.0f / csk;
#pragma unroll 4
    for (int d = 0; d < 64; d++) {
        float e = DECAY * ema_in[k * 64 + d] + OMD * g_dw[k * 64 + d];
        out[OUT_EMA + k * 64 + d] = e;
        out[OUT_CB + k * 64 + d]  = e * inv;
    }
    if (k == 0) out[OUT_LOSS] = g_loss * (1.0f / (float)(N_TOKENS * CODE_DIM));
}

extern "C" void kernel_launch(void* const* d_in, const int* in_sizes, int n_in,
                              void* d_out, int out_size) {
    const float* z   = (const float*)d_in[0];
    const float* cb  = (const float*)d_in[1];
    const float* cs  = (const float*)d_in[2];
    const float* ema = (const float*)d_in[3];
    float* out = (float*)d_out;

    prep_cb_kernel<<<64, 256>>>((const float4*)cb);
    prep_z_kernel<<<8192, 256>>>((const float4*)z);
    assign_kernel<<<1024, 128>>>((const float4*)z, (const float4*)cb, out);
    finalize_kernel<<<1, 1024>>>(cs, ema, out);
}